// round 1
// baseline (speedup 1.0000x reference)
#include <cuda_runtime.h>
#include <math.h>
#include <float.h>

// Problem constants
#define NB   2
#define CC   128
#define HH   64
#define WW   64
#define HS   128
#define WS   128
#define HP   62          // HH - 2
#define USZ  126         // HS - 2
#define M_R  4096        // HH*WW   (ref pixels per image)
#define N_S  16384       // HS*WS   (shape pixels per image)

// Scratch: pixel-pair Gram matrix T[n][r][s] and per-pixel argmax index.
static __device__ float g_T[(size_t)NB * M_R * N_S];   // 537 MB
static __device__ int   g_idx[NB * HP * HP];

// ---------------------------------------------------------------------------
// Kernel 0: zero the output scalar(s)
// ---------------------------------------------------------------------------
__global__ void zero_kernel(float* out, int n) {
    for (int i = threadIdx.x; i < n; i += blockDim.x) out[i] = 0.0f;
}

// ---------------------------------------------------------------------------
// Kernel 1: T[n,r,s] = sum_c ref[n,c,r] * shape[n,c,s]
// Classic fp32 SGEMM, 128x128 block tile, K-chunk 16, 8x8 per thread.
// A (ref) and B (shape) are both K-major (c outer), so tile loads are
// contiguous along r / s -> fully coalesced.
// ---------------------------------------------------------------------------
#define BM 128
#define BN 128
#define BK 16

__global__ __launch_bounds__(256) void gemm_kernel(const float* __restrict__ reff,
                                                   const float* __restrict__ shapef) {
    __shared__ float As[BK][BM];
    __shared__ float Bs[BK][BN];

    const int n  = blockIdx.z;
    const float* A  = reff   + (size_t)n * CC * M_R;   // A[c*M_R + r]
    const float* B  = shapef + (size_t)n * CC * N_S;   // B[c*N_S + s]
    float*       Ct = g_T    + (size_t)n * M_R * N_S;  // C[r*N_S + s]

    const int r0 = blockIdx.y * BM;
    const int s0 = blockIdx.x * BN;
    const int tid = threadIdx.x;
    const int tx = tid & 15;          // 0..15 -> 8 cols each
    const int ty = tid >> 4;          // 0..15 -> 8 rows each

    float acc[8][8];
#pragma unroll
    for (int i = 0; i < 8; i++)
#pragma unroll
        for (int j = 0; j < 8; j++) acc[i][j] = 0.0f;

    for (int kk = 0; kk < CC; kk += BK) {
        // Cooperative tile loads (coalesced along m)
#pragma unroll
        for (int idx = tid; idx < BK * BM; idx += 256) {
            int k = idx >> 7;         // /128
            int m = idx & 127;
            As[k][m] = A[(size_t)(kk + k) * M_R + r0 + m];
        }
#pragma unroll
        for (int idx = tid; idx < BK * BN; idx += 256) {
            int k = idx >> 7;
            int m = idx & 127;
            Bs[k][m] = B[(size_t)(kk + k) * N_S + s0 + m];
        }
        __syncthreads();

#pragma unroll
        for (int k = 0; k < BK; k++) {
            float ra[8], rb[8];
#pragma unroll
            for (int i = 0; i < 8; i++) ra[i] = As[k][ty * 8 + i];
#pragma unroll
            for (int j = 0; j < 8; j++) rb[j] = Bs[k][tx * 8 + j];
#pragma unroll
            for (int i = 0; i < 8; i++)
#pragma unroll
                for (int j = 0; j < 8; j++)
                    acc[i][j] += ra[i] * rb[j];
        }
        __syncthreads();
    }

    // Store 8x8 with float4 vectorization
#pragma unroll
    for (int i = 0; i < 8; i++) {
        float4* dst = (float4*)(Ct + (size_t)(r0 + ty * 8 + i) * N_S + s0 + tx * 8);
        dst[0] = make_float4(acc[i][0], acc[i][1], acc[i][2], acc[i][3]);
        dst[1] = make_float4(acc[i][4], acc[i][5], acc[i][6], acc[i][7]);
    }
}

// ---------------------------------------------------------------------------
// Kernel 2: per-pixel argmax over all 126x126 shape-patch positions.
// sim[(i,j),(us,vs)] = sum_{a,b in 0..2} T[(i+a, j+b), (us+a, vs+b)]
// One block per (n,i,j). Strided scan over u; block reduce (max, first idx).
// Consecutive blockIdx.x share i -> 12MB working set lives in L2.
// ---------------------------------------------------------------------------
__global__ __launch_bounds__(256) void argmax_kernel() {
    const int j = blockIdx.x;
    const int i = blockIdx.y;
    const int n = blockIdx.z;

    const float* Tn = g_T + (size_t)n * M_R * N_S;
    const float* row[3][3];
#pragma unroll
    for (int a = 0; a < 3; a++)
#pragma unroll
        for (int b = 0; b < 3; b++)
            row[a][b] = Tn + (size_t)((i + a) * WW + (j + b)) * N_S;

    float best = -FLT_MAX;
    int   bidx = 0;

    for (int u = threadIdx.x; u < USZ * USZ; u += 256) {
        int us = u / USZ;
        int vs = u - us * USZ;
        int base = us * WS + vs;
        float s = 0.0f;
#pragma unroll
        for (int a = 0; a < 3; a++)
#pragma unroll
            for (int b = 0; b < 3; b++)
                s += row[a][b][base + a * WS + b];
        if (s > best) { best = s; bidx = u; }   // strict > keeps first occurrence
    }

    // Block reduction: max value; ties -> smallest index
    __shared__ float sv[256];
    __shared__ int   si[256];
    sv[threadIdx.x] = best;
    si[threadIdx.x] = bidx;
    __syncthreads();
    for (int off = 128; off > 0; off >>= 1) {
        if (threadIdx.x < off) {
            float ov = sv[threadIdx.x + off];
            int   oi = si[threadIdx.x + off];
            if (ov > sv[threadIdx.x] ||
                (ov == sv[threadIdx.x] && oi < si[threadIdx.x])) {
                sv[threadIdx.x] = ov;
                si[threadIdx.x] = oi;
            }
        }
        __syncthreads();
    }
    if (threadIdx.x == 0)
        g_idx[(n * HP + i) * HP + j] = si[0];
}

// ---------------------------------------------------------------------------
// Kernel 3: gather matched color patch, L1 vs output patch, clip, global sum.
// One block per (i, n); threads iterate (c, j) with j fastest -> coalesced
// reads of output_feat; color reads are scattered 3-float segments.
// ---------------------------------------------------------------------------
__global__ __launch_bounds__(256) void l1_kernel(const float* __restrict__ outf,
                                                 const float* __restrict__ colf,
                                                 float* __restrict__ dout) {
    const int i = blockIdx.x;
    const int n = blockIdx.y;

    __shared__ float l1s[HP];
    __shared__ int   uu[HP];
    if (threadIdx.x < HP) {
        l1s[threadIdx.x] = 0.0f;
        uu[threadIdx.x]  = g_idx[(n * HP + i) * HP + threadIdx.x];
    }
    __syncthreads();

    for (int t = threadIdx.x; t < CC * HP; t += 256) {
        int c = t / HP;
        int j = t - c * HP;
        int u  = uu[j];
        int us = u / USZ;
        int vs = u - us * USZ;

        const float* op = outf + ((size_t)(n * CC + c) * HH + i)  * WW + j;
        const float* cp = colf + ((size_t)(n * CC + c) * HS + us) * WS + vs;

        float s = 0.0f;
#pragma unroll
        for (int a = 0; a < 3; a++)
#pragma unroll
            for (int b = 0; b < 3; b++)
                s += fabsf(op[a * WW + b] - cp[a * WS + b]);
        atomicAdd(&l1s[j], s);
    }
    __syncthreads();

    if (threadIdx.x < HP) {
        float v = fminf(fmaxf(l1s[threadIdx.x], 0.0f), 1000.0f);
        atomicAdd(dout, v);
    }
}

// ---------------------------------------------------------------------------
// Launch
// Inputs (metadata order): 0 output_feat, 1 ref_feat, 2 shape_feat, 3 color_feat
// ---------------------------------------------------------------------------
extern "C" void kernel_launch(void* const* d_in, const int* in_sizes, int n_in,
                              void* d_out, int out_size) {
    const float* output_feat = (const float*)d_in[0];
    const float* ref_feat    = (const float*)d_in[1];
    const float* shape_feat  = (const float*)d_in[2];
    const float* color_feat  = (const float*)d_in[3];
    float* out = (float*)d_out;

    zero_kernel<<<1, 32>>>(out, out_size);

    dim3 g1(N_S / BN, M_R / BM, NB);            // 128 x 32 x 2
    gemm_kernel<<<g1, 256>>>(ref_feat, shape_feat);

    dim3 g2(HP, HP, NB);                        // 62 x 62 x 2
    argmax_kernel<<<g2, 256>>>();

    dim3 g3(HP, NB);                            // 62 x 2
    l1_kernel<<<g3, 256>>>(output_feat, color_feat, out);
}

// round 2
// speedup vs baseline: 1.0064x; 1.0064x over previous
#include <cuda_runtime.h>
#include <math.h>
#include <float.h>

// Problem constants
#define NB   2
#define CC   128
#define HH   64
#define WW   64
#define HS   128
#define WS   128
#define HP   62          // HH - 2
#define USZ  126         // HS - 2
#define M_R  4096        // HH*WW   (ref pixels per image)
#define N_S  16384       // HS*WS   (shape pixels per image)

// Scratch: pixel-pair Gram matrix T[n][r][s] and per-pixel argmax index.
static __device__ float g_T[(size_t)NB * M_R * N_S];   // 537 MB
static __device__ int   g_idx[NB * HP * HP];

// ---------------------------------------------------------------------------
// Kernel 0: zero the output scalar(s)
// ---------------------------------------------------------------------------
__global__ void zero_kernel(float* out, int n) {
    for (int i = threadIdx.x; i < n; i += blockDim.x) out[i] = 0.0f;
}

// ---------------------------------------------------------------------------
// Kernel 1: T[n,r,s] = sum_c ref[n,c,r] * shape[n,c,s]
// Classic fp32 SGEMM, 128x128 block tile, K-chunk 16, 8x8 per thread.
// A (ref) and B (shape) are both K-major (c outer), so tile loads are
// contiguous along r / s -> fully coalesced.
// ---------------------------------------------------------------------------
#define BM 128
#define BN 128
#define BK 16

__global__ __launch_bounds__(256) void gemm_kernel(const float* __restrict__ reff,
                                                   const float* __restrict__ shapef) {
    __shared__ float As[BK][BM];
    __shared__ float Bs[BK][BN];

    const int n  = blockIdx.z;
    const float* A  = reff   + (size_t)n * CC * M_R;   // A[c*M_R + r]
    const float* B  = shapef + (size_t)n * CC * N_S;   // B[c*N_S + s]
    float*       Ct = g_T    + (size_t)n * M_R * N_S;  // C[r*N_S + s]

    const int r0 = blockIdx.y * BM;
    const int s0 = blockIdx.x * BN;
    const int tid = threadIdx.x;
    const int tx = tid & 15;          // 0..15 -> 8 cols each
    const int ty = tid >> 4;          // 0..15 -> 8 rows each

    float acc[8][8];
#pragma unroll
    for (int i = 0; i < 8; i++)
#pragma unroll
        for (int j = 0; j < 8; j++) acc[i][j] = 0.0f;

    for (int kk = 0; kk < CC; kk += BK) {
        // Cooperative tile loads (coalesced along m)
#pragma unroll
        for (int idx = tid; idx < BK * BM; idx += 256) {
            int k = idx >> 7;         // /128
            int m = idx & 127;
            As[k][m] = A[(size_t)(kk + k) * M_R + r0 + m];
        }
#pragma unroll
        for (int idx = tid; idx < BK * BN; idx += 256) {
            int k = idx >> 7;
            int m = idx & 127;
            Bs[k][m] = B[(size_t)(kk + k) * N_S + s0 + m];
        }
        __syncthreads();

#pragma unroll
        for (int k = 0; k < BK; k++) {
            float ra[8], rb[8];
#pragma unroll
            for (int i = 0; i < 8; i++) ra[i] = As[k][ty * 8 + i];
#pragma unroll
            for (int j = 0; j < 8; j++) rb[j] = Bs[k][tx * 8 + j];
#pragma unroll
            for (int i = 0; i < 8; i++)
#pragma unroll
                for (int j = 0; j < 8; j++)
                    acc[i][j] += ra[i] * rb[j];
        }
        __syncthreads();
    }

    // Store 8x8 with float4 vectorization
#pragma unroll
    for (int i = 0; i < 8; i++) {
        float4* dst = (float4*)(Ct + (size_t)(r0 + ty * 8 + i) * N_S + s0 + tx * 8);
        dst[0] = make_float4(acc[i][0], acc[i][1], acc[i][2], acc[i][3]);
        dst[1] = make_float4(acc[i][4], acc[i][5], acc[i][6], acc[i][7]);
    }
}

// ---------------------------------------------------------------------------
// Kernel 2: per-pixel argmax over all 126x126 shape-patch positions.
// sim[(i,j),(us,vs)] = sum_{a,b in 0..2} T[(i+a, j+b), (us+a, vs+b)]
// One block per (n,i,j). Strided scan over u; block reduce (max, first idx).
// Consecutive blockIdx.x share i -> 12MB working set lives in L2.
// ---------------------------------------------------------------------------
__global__ __launch_bounds__(256) void argmax_kernel() {
    const int j = blockIdx.x;
    const int i = blockIdx.y;
    const int n = blockIdx.z;

    const float* Tn = g_T + (size_t)n * M_R * N_S;
    const float* row[3][3];
#pragma unroll
    for (int a = 0; a < 3; a++)
#pragma unroll
        for (int b = 0; b < 3; b++)
            row[a][b] = Tn + (size_t)((i + a) * WW + (j + b)) * N_S;

    float best = -FLT_MAX;
    int   bidx = 0;

    for (int u = threadIdx.x; u < USZ * USZ; u += 256) {
        int us = u / USZ;
        int vs = u - us * USZ;
        int base = us * WS + vs;
        float s = 0.0f;
#pragma unroll
        for (int a = 0; a < 3; a++)
#pragma unroll
            for (int b = 0; b < 3; b++)
                s += row[a][b][base + a * WS + b];
        if (s > best) { best = s; bidx = u; }   // strict > keeps first occurrence
    }

    // Block reduction: max value; ties -> smallest index
    __shared__ float sv[256];
    __shared__ int   si[256];
    sv[threadIdx.x] = best;
    si[threadIdx.x] = bidx;
    __syncthreads();
    for (int off = 128; off > 0; off >>= 1) {
        if (threadIdx.x < off) {
            float ov = sv[threadIdx.x + off];
            int   oi = si[threadIdx.x + off];
            if (ov > sv[threadIdx.x] ||
                (ov == sv[threadIdx.x] && oi < si[threadIdx.x])) {
                sv[threadIdx.x] = ov;
                si[threadIdx.x] = oi;
            }
        }
        __syncthreads();
    }
    if (threadIdx.x == 0)
        g_idx[(n * HP + i) * HP + j] = si[0];
}

// ---------------------------------------------------------------------------
// Kernel 3: gather matched color patch, L1 vs output patch, clip, global sum.
// One block per (i, n); threads iterate (c, j) with j fastest -> coalesced
// reads of output_feat; color reads are scattered 3-float segments.
// ---------------------------------------------------------------------------
__global__ __launch_bounds__(256) void l1_kernel(const float* __restrict__ outf,
                                                 const float* __restrict__ colf,
                                                 float* __restrict__ dout) {
    const int i = blockIdx.x;
    const int n = blockIdx.y;

    __shared__ float l1s[HP];
    __shared__ int   uu[HP];
    if (threadIdx.x < HP) {
        l1s[threadIdx.x] = 0.0f;
        uu[threadIdx.x]  = g_idx[(n * HP + i) * HP + threadIdx.x];
    }
    __syncthreads();

    for (int t = threadIdx.x; t < CC * HP; t += 256) {
        int c = t / HP;
        int j = t - c * HP;
        int u  = uu[j];
        int us = u / USZ;
        int vs = u - us * USZ;

        const float* op = outf + ((size_t)(n * CC + c) * HH + i)  * WW + j;
        const float* cp = colf + ((size_t)(n * CC + c) * HS + us) * WS + vs;

        float s = 0.0f;
#pragma unroll
        for (int a = 0; a < 3; a++)
#pragma unroll
            for (int b = 0; b < 3; b++)
                s += fabsf(op[a * WW + b] - cp[a * WS + b]);
        atomicAdd(&l1s[j], s);
    }
    __syncthreads();

    if (threadIdx.x < HP) {
        float v = fminf(fmaxf(l1s[threadIdx.x], 0.0f), 1000.0f);
        atomicAdd(dout, v);
    }
}

// ---------------------------------------------------------------------------
// Launch
// Inputs (metadata order): 0 output_feat, 1 ref_feat, 2 shape_feat, 3 color_feat
// ---------------------------------------------------------------------------
extern "C" void kernel_launch(void* const* d_in, const int* in_sizes, int n_in,
                              void* d_out, int out_size) {
    const float* output_feat = (const float*)d_in[0];
    const float* ref_feat    = (const float*)d_in[1];
    const float* shape_feat  = (const float*)d_in[2];
    const float* color_feat  = (const float*)d_in[3];
    float* out = (float*)d_out;

    zero_kernel<<<1, 32>>>(out, out_size);

    dim3 g1(N_S / BN, M_R / BM, NB);            // 128 x 32 x 2
    gemm_kernel<<<g1, 256>>>(ref_feat, shape_feat);

    dim3 g2(HP, HP, NB);                        // 62 x 62 x 2
    argmax_kernel<<<g2, 256>>>();

    dim3 g3(HP, NB);                            // 62 x 2
    l1_kernel<<<g3, 256>>>(output_feat, color_feat, out);
}

// round 3
// speedup vs baseline: 2.5977x; 2.5812x over previous
#include <cuda_runtime.h>
#include <cuda_bf16.h>
#include <math.h>
#include <float.h>
#include <stdint.h>

// Problem constants
#define NB   2
#define CC   128
#define HH   64
#define WW   64
#define HS   128
#define WS   128
#define HP   62          // HH - 2
#define USZ  126         // HS - 2
#define M_R  4096        // HH*WW   (ref pixels per image)
#define N_S  16384       // HS*WS   (shape pixels per image)

// Scratch: pixel-pair Gram matrix T (bf16) and per-pixel argmax index.
static __device__ __nv_bfloat16 g_Tb[(size_t)NB * M_R * N_S];   // 268 MB
static __device__ int           g_idx[NB * HP * HP];

// ---------------------------------------------------------------------------
// Kernel 0: zero the output scalar(s)
// ---------------------------------------------------------------------------
__global__ void zero_kernel(float* out, int n) {
    for (int i = threadIdx.x; i < n; i += blockDim.x) out[i] = 0.0f;
}

// ---------------------------------------------------------------------------
// Kernel 1: T[n,r,s] = sum_c ref[n,c,r] * shape[n,c,s]   (bf16 HMMA, f32 acc)
// 128x128 block tile, BK=32 (stored as 16 rows of bf162 k-pairs).
// 8 warps: 2(m) x 4(n), each warp computes 64x32 via m16n8k16 mma.sync.
// Smem layout As2[k2][m] holds bf162(k=2*k2, k=2*k2+1) for column m, row
// stride 132 u32 to kill the 4-way tid4 bank conflict on fragment loads.
// ---------------------------------------------------------------------------
#define BM 128
#define BN 128
#define BK2 16          // BK/2 = 16 k-pair rows per stage (BK = 32)
#define SPITCH 132      // padded row stride in u32

__global__ __launch_bounds__(256) void gemm_kernel(const float* __restrict__ reff,
                                                   const float* __restrict__ shapef) {
    __shared__ __align__(16) uint32_t As2[BK2 * SPITCH];
    __shared__ __align__(16) uint32_t Bs2[BK2 * SPITCH];

    const int n  = blockIdx.z;
    const float* A = reff   + (size_t)n * CC * M_R;   // A[c*M_R + r]
    const float* B = shapef + (size_t)n * CC * N_S;   // B[c*N_S + s]
    __nv_bfloat16* Ct = g_Tb + (size_t)n * M_R * N_S; // C[r*N_S + s]

    const int r0 = blockIdx.y * BM;
    const int s0 = blockIdx.x * BN;
    const int tid  = threadIdx.x;
    const int lane = tid & 31;
    const int wid  = tid >> 5;
    const int warp_m = (wid >> 2) * 64;   // 0 or 64
    const int warp_n = (wid & 3) * 32;    // 0,32,64,96
    const int g    = lane >> 2;           // 0..7
    const int tid4 = lane & 3;            // 0..3

    float acc[4][4][4];
#pragma unroll
    for (int mt = 0; mt < 4; mt++)
#pragma unroll
        for (int nt = 0; nt < 4; nt++)
#pragma unroll
            for (int q = 0; q < 4; q++) acc[mt][nt][q] = 0.0f;

    for (int kk = 0; kk < CC; kk += 2 * BK2) {
        // ---- cooperative load + fp32->bf162 convert ----
#pragma unroll
        for (int idx = tid; idx < BK2 * BM; idx += 256) {
            int k2 = idx >> 7;          // /128
            int m  = idx & 127;
            float a0 = A[(size_t)(kk + 2 * k2)     * M_R + r0 + m];
            float a1 = A[(size_t)(kk + 2 * k2 + 1) * M_R + r0 + m];
            __nv_bfloat162 h = __floats2bfloat162_rn(a0, a1);
            As2[k2 * SPITCH + m] = *(uint32_t*)&h;
            float b0 = B[(size_t)(kk + 2 * k2)     * N_S + s0 + m];
            float b1 = B[(size_t)(kk + 2 * k2 + 1) * N_S + s0 + m];
            __nv_bfloat162 hb = __floats2bfloat162_rn(b0, b1);
            Bs2[k2 * SPITCH + m] = *(uint32_t*)&hb;
        }
        __syncthreads();

        // ---- two k16 chunks per stage ----
#pragma unroll
        for (int kc2 = 0; kc2 < BK2; kc2 += 8) {
            uint32_t af[4][4], bfr[4][2];
#pragma unroll
            for (int mt = 0; mt < 4; mt++) {
                int m = warp_m + mt * 16 + g;
                af[mt][0] = As2[(kc2 + tid4)     * SPITCH + m];
                af[mt][1] = As2[(kc2 + tid4)     * SPITCH + m + 8];
                af[mt][2] = As2[(kc2 + tid4 + 4) * SPITCH + m];
                af[mt][3] = As2[(kc2 + tid4 + 4) * SPITCH + m + 8];
            }
#pragma unroll
            for (int nt = 0; nt < 4; nt++) {
                int nn = warp_n + nt * 8 + g;
                bfr[nt][0] = Bs2[(kc2 + tid4)     * SPITCH + nn];
                bfr[nt][1] = Bs2[(kc2 + tid4 + 4) * SPITCH + nn];
            }
#pragma unroll
            for (int mt = 0; mt < 4; mt++)
#pragma unroll
                for (int nt = 0; nt < 4; nt++) {
                    asm volatile(
                        "mma.sync.aligned.m16n8k16.row.col.f32.bf16.bf16.f32 "
                        "{%0,%1,%2,%3},{%4,%5,%6,%7},{%8,%9},{%0,%1,%2,%3};"
                        : "+f"(acc[mt][nt][0]), "+f"(acc[mt][nt][1]),
                          "+f"(acc[mt][nt][2]), "+f"(acc[mt][nt][3])
                        : "r"(af[mt][0]), "r"(af[mt][1]), "r"(af[mt][2]), "r"(af[mt][3]),
                          "r"(bfr[nt][0]), "r"(bfr[nt][1]));
                }
        }
        __syncthreads();
    }

    // ---- epilogue: f32 acc -> bf162 stores ----
    // c0:(row g, col 2t) c1:(g, 2t+1) c2:(g+8, 2t) c3:(g+8, 2t+1)
#pragma unroll
    for (int mt = 0; mt < 4; mt++) {
#pragma unroll
        for (int nt = 0; nt < 4; nt++) {
            int row = r0 + warp_m + mt * 16 + g;
            int col = s0 + warp_n + nt * 8 + 2 * tid4;
            __nv_bfloat162 lo = __floats2bfloat162_rn(acc[mt][nt][0], acc[mt][nt][1]);
            __nv_bfloat162 hi = __floats2bfloat162_rn(acc[mt][nt][2], acc[mt][nt][3]);
            *(__nv_bfloat162*)(Ct + (size_t)row * N_S + col)       = lo;
            *(__nv_bfloat162*)(Ct + (size_t)(row + 8) * N_S + col) = hi;
        }
    }
}

// ---------------------------------------------------------------------------
// Kernel 2: per-pixel argmax over all 126x126 shape-patch positions.
// sim[(i,j),(us,vs)] = sum_{a,b} T[(i+a, j+b)][(us+a)*128 + (vs+b)]
// Each thread computes 4 consecutive vs from shared 6-wide bf162 windows.
// ---------------------------------------------------------------------------
__global__ __launch_bounds__(256) void argmax_kernel() {
    const int j = blockIdx.x;
    const int i = blockIdx.y;
    const int n = blockIdx.z;

    const __nv_bfloat16* Tn = g_Tb + (size_t)n * M_R * N_S;
    const __nv_bfloat16* rowp[3][3];
#pragma unroll
    for (int a = 0; a < 3; a++)
#pragma unroll
        for (int b = 0; b < 3; b++)
            rowp[a][b] = Tn + (size_t)((i + a) * WW + (j + b)) * N_S;

    float best = -FLT_MAX;
    int   bidx = 0;

    for (int idx = threadIdx.x; idx < USZ * 32; idx += 256) {
        int us  = idx >> 5;
        int grp = idx & 31;
        int vs0 = grp << 2;

        float s[4] = {0.0f, 0.0f, 0.0f, 0.0f};
        bool full = (grp < 31);   // grp 31 -> only vs 124,125 valid
#pragma unroll
        for (int a = 0; a < 3; a++) {
            int base = (us + a) * WS + vs0;
#pragma unroll
            for (int b = 0; b < 3; b++) {
                const __nv_bfloat162* p2 =
                    (const __nv_bfloat162*)(rowp[a][b] + base);
                float2 w0 = __bfloat1622float2(p2[0]);
                float2 w1 = __bfloat1622float2(p2[1]);
                float2 w2 = full ? __bfloat1622float2(p2[2])
                                 : make_float2(0.0f, 0.0f);
                float f[6] = {w0.x, w0.y, w1.x, w1.y, w2.x, w2.y};
                s[0] += f[b];
                s[1] += f[b + 1];
                s[2] += f[b + 2];
                s[3] += f[b + 3];
            }
        }
#pragma unroll
        for (int d = 0; d < 4; d++) {
            if (vs0 + d < USZ) {
                if (s[d] > best) { best = s[d]; bidx = us * USZ + vs0 + d; }
            }
        }
    }

    // Block reduction: max value; ties -> smallest index (first occurrence)
    __shared__ float sv[256];
    __shared__ int   si[256];
    sv[threadIdx.x] = best;
    si[threadIdx.x] = bidx;
    __syncthreads();
    for (int off = 128; off > 0; off >>= 1) {
        if (threadIdx.x < off) {
            float ov = sv[threadIdx.x + off];
            int   oi = si[threadIdx.x + off];
            if (ov > sv[threadIdx.x] ||
                (ov == sv[threadIdx.x] && oi < si[threadIdx.x])) {
                sv[threadIdx.x] = ov;
                si[threadIdx.x] = oi;
            }
        }
        __syncthreads();
    }
    if (threadIdx.x == 0)
        g_idx[(n * HP + i) * HP + j] = si[0];
}

// ---------------------------------------------------------------------------
// Kernel 3: gather matched color patch, L1 vs output patch, clip, global sum.
// ---------------------------------------------------------------------------
__global__ __launch_bounds__(256) void l1_kernel(const float* __restrict__ outf,
                                                 const float* __restrict__ colf,
                                                 float* __restrict__ dout) {
    const int i = blockIdx.x;
    const int n = blockIdx.y;

    __shared__ float l1s[HP];
    __shared__ int   uu[HP];
    if (threadIdx.x < HP) {
        l1s[threadIdx.x] = 0.0f;
        uu[threadIdx.x]  = g_idx[(n * HP + i) * HP + threadIdx.x];
    }
    __syncthreads();

    for (int t = threadIdx.x; t < CC * HP; t += 256) {
        int c = t / HP;
        int j = t - c * HP;
        int u  = uu[j];
        int us = u / USZ;
        int vs = u - us * USZ;

        const float* op = outf + ((size_t)(n * CC + c) * HH + i)  * WW + j;
        const float* cp = colf + ((size_t)(n * CC + c) * HS + us) * WS + vs;

        float s = 0.0f;
#pragma unroll
        for (int a = 0; a < 3; a++)
#pragma unroll
            for (int b = 0; b < 3; b++)
                s += fabsf(op[a * WW + b] - cp[a * WS + b]);
        atomicAdd(&l1s[j], s);
    }
    __syncthreads();

    if (threadIdx.x < HP) {
        float v = fminf(fmaxf(l1s[threadIdx.x], 0.0f), 1000.0f);
        atomicAdd(dout, v);
    }
}

// ---------------------------------------------------------------------------
// Launch
// Inputs (metadata order): 0 output_feat, 1 ref_feat, 2 shape_feat, 3 color_feat
// ---------------------------------------------------------------------------
extern "C" void kernel_launch(void* const* d_in, const int* in_sizes, int n_in,
                              void* d_out, int out_size) {
    const float* output_feat = (const float*)d_in[0];
    const float* ref_feat    = (const float*)d_in[1];
    const float* shape_feat  = (const float*)d_in[2];
    const float* color_feat  = (const float*)d_in[3];
    float* out = (float*)d_out;

    zero_kernel<<<1, 32>>>(out, out_size);

    dim3 g1(N_S / BN, M_R / BM, NB);            // 128 x 32 x 2
    gemm_kernel<<<g1, 256>>>(ref_feat, shape_feat);

    dim3 g2(HP, HP, NB);                        // 62 x 62 x 2
    argmax_kernel<<<g2, 256>>>();

    dim3 g3(HP, NB);                            // 62 x 2
    l1_kernel<<<g3, 256>>>(output_feat, color_feat, out);
}

// round 4
// speedup vs baseline: 2.6657x; 1.0261x over previous
#include <cuda_runtime.h>
#include <cuda_bf16.h>
#include <math.h>
#include <float.h>
#include <stdint.h>

// Problem constants
#define NB   2
#define CC   128
#define HH   64
#define WW   64
#define HS   128
#define WS   128
#define HP   62          // HH - 2
#define USZ  126         // HS - 2
#define M_R  4096        // HH*WW   (ref pixels per image)
#define N_S  16384       // HS*WS   (shape pixels per image)

// Scratch
static __device__ __nv_bfloat16 g_Tb[(size_t)NB * M_R * N_S];     // 268 MB Gram matrix
static __device__ uint32_t      g_Apk[(size_t)NB * (CC/2) * M_R]; // 2 MB  bf162 k-pair packed ref
static __device__ uint32_t      g_Bpk[(size_t)NB * (CC/2) * N_S]; // 8 MB  bf162 k-pair packed shape
static __device__ int           g_idx[NB * HP * HP];

// ---------------------------------------------------------------------------
// Kernel 0: zero the output scalar(s)
// ---------------------------------------------------------------------------
__global__ void zero_kernel(float* out, int n) {
    for (int i = threadIdx.x; i < n; i += blockDim.x) out[i] = 0.0f;
}

// ---------------------------------------------------------------------------
// Kernel 0b: pack fp32 [n][c][m] -> bf162 k-pair layout [n][k2][m]
// dst[x] where x = (n*64 + k2)*M + m  holds bf162(c=2k2, c=2k2+1) of pixel m.
// ---------------------------------------------------------------------------
__global__ void pack_kernel(const float* __restrict__ src, uint32_t* __restrict__ dst,
                            int M, int total) {
    for (int x = blockIdx.x * blockDim.x + threadIdx.x; x < total;
         x += gridDim.x * blockDim.x) {
        int m   = x % M;
        int nk2 = x / M;
        int n   = nk2 >> 6;       // /64
        int k2  = nk2 & 63;
        const float* s = src + ((size_t)(n * CC + 2 * k2)) * M + m;
        __nv_bfloat162 h = __floats2bfloat162_rn(s[0], s[M]);
        dst[x] = *(uint32_t*)&h;
    }
}

// ---------------------------------------------------------------------------
// Kernel 1: T[n,r,s] = sum_c ref[n,c,r] * shape[n,c,s]   (bf16 HMMA, f32 acc)
// 128x128 block tile, BK=32 (16 bf162 k-pair rows per stage), double-buffered
// cp.async pipeline. 8 warps 2(m)x4(n), each 64x32 via m16n8k16.
// ---------------------------------------------------------------------------
#define BM 128
#define BN 128
#define BK2 16          // k-pair rows per stage (BK = 32)
#define SPITCH 132      // padded row stride in u32 (132*4=528 bytes, 16B-multiple)

__device__ __forceinline__ void cp_async16(uint32_t smem_addr, const void* gptr) {
    asm volatile("cp.async.cg.shared.global [%0], [%1], 16;\n"
                 :: "r"(smem_addr), "l"(gptr));
}

__global__ __launch_bounds__(256) void gemm_kernel() {
    __shared__ __align__(16) uint32_t As2[2][BK2 * SPITCH];
    __shared__ __align__(16) uint32_t Bs2[2][BK2 * SPITCH];

    const int n = blockIdx.z;
    const uint32_t* Ap = g_Apk + (size_t)n * (CC / 2) * M_R;
    const uint32_t* Bp = g_Bpk + (size_t)n * (CC / 2) * N_S;
    __nv_bfloat16*  Ct = g_Tb  + (size_t)n * M_R * N_S;

    const int r0 = blockIdx.y * BM;
    const int s0 = blockIdx.x * BN;
    const int tid  = threadIdx.x;
    const int lane = tid & 31;
    const int wid  = tid >> 5;
    const int warp_m = (wid >> 2) * 64;
    const int warp_n = (wid & 3) * 32;
    const int g    = lane >> 2;
    const int tid4 = lane & 3;

    const uint32_t sA = (uint32_t)__cvta_generic_to_shared(&As2[0][0]);
    const uint32_t sB = (uint32_t)__cvta_generic_to_shared(&Bs2[0][0]);

    // issue one stage of cp.async (A and B tiles), 2 chunks of 16B per thread each
    auto issue = [&](int buf, int kk2) {
#pragma unroll
        for (int h = 0; h < 2; h++) {
            int ch = tid + h * 256;          // 0..511
            int k2 = ch >> 5;                // 0..15
            int m4 = (ch & 31) << 2;         // u32 offset, 16B granules
            uint32_t doff = (uint32_t)((buf * BK2 * SPITCH + k2 * SPITCH + m4) * 4);
            cp_async16(sA + doff, Ap + (size_t)(kk2 + k2) * M_R + r0 + m4);
            cp_async16(sB + doff, Bp + (size_t)(kk2 + k2) * N_S + s0 + m4);
        }
        asm volatile("cp.async.commit_group;\n" ::: "memory");
    };

    float acc[4][4][4];
#pragma unroll
    for (int mt = 0; mt < 4; mt++)
#pragma unroll
        for (int nt = 0; nt < 4; nt++)
#pragma unroll
            for (int q = 0; q < 4; q++) acc[mt][nt][q] = 0.0f;

    issue(0, 0);

    const int NSTAGE = (CC / 2) / BK2;   // 4
#pragma unroll
    for (int s = 0; s < NSTAGE; s++) {
        if (s + 1 < NSTAGE) {
            issue((s + 1) & 1, (s + 1) * BK2);
            asm volatile("cp.async.wait_group 1;\n" ::: "memory");
        } else {
            asm volatile("cp.async.wait_group 0;\n" ::: "memory");
        }
        __syncthreads();

        const uint32_t* Ab = &As2[s & 1][0];
        const uint32_t* Bb = &Bs2[s & 1][0];
#pragma unroll
        for (int kc2 = 0; kc2 < BK2; kc2 += 8) {
            uint32_t af[4][4], bfr[4][2];
#pragma unroll
            for (int mt = 0; mt < 4; mt++) {
                int m = warp_m + mt * 16 + g;
                af[mt][0] = Ab[(kc2 + tid4)     * SPITCH + m];
                af[mt][1] = Ab[(kc2 + tid4)     * SPITCH + m + 8];
                af[mt][2] = Ab[(kc2 + tid4 + 4) * SPITCH + m];
                af[mt][3] = Ab[(kc2 + tid4 + 4) * SPITCH + m + 8];
            }
#pragma unroll
            for (int nt = 0; nt < 4; nt++) {
                int nn = warp_n + nt * 8 + g;
                bfr[nt][0] = Bb[(kc2 + tid4)     * SPITCH + nn];
                bfr[nt][1] = Bb[(kc2 + tid4 + 4) * SPITCH + nn];
            }
#pragma unroll
            for (int mt = 0; mt < 4; mt++)
#pragma unroll
                for (int nt = 0; nt < 4; nt++) {
                    asm volatile(
                        "mma.sync.aligned.m16n8k16.row.col.f32.bf16.bf16.f32 "
                        "{%0,%1,%2,%3},{%4,%5,%6,%7},{%8,%9},{%0,%1,%2,%3};"
                        : "+f"(acc[mt][nt][0]), "+f"(acc[mt][nt][1]),
                          "+f"(acc[mt][nt][2]), "+f"(acc[mt][nt][3])
                        : "r"(af[mt][0]), "r"(af[mt][1]), "r"(af[mt][2]), "r"(af[mt][3]),
                          "r"(bfr[nt][0]), "r"(bfr[nt][1]));
                }
        }
        __syncthreads();
    }

    // Epilogue: f32 acc -> bf162 stores
#pragma unroll
    for (int mt = 0; mt < 4; mt++) {
#pragma unroll
        for (int nt = 0; nt < 4; nt++) {
            int row = r0 + warp_m + mt * 16 + g;
            int col = s0 + warp_n + nt * 8 + 2 * tid4;
            __nv_bfloat162 lo = __floats2bfloat162_rn(acc[mt][nt][0], acc[mt][nt][1]);
            __nv_bfloat162 hi = __floats2bfloat162_rn(acc[mt][nt][2], acc[mt][nt][3]);
            *(__nv_bfloat162*)(Ct + (size_t)row * N_S + col)       = lo;
            *(__nv_bfloat162*)(Ct + (size_t)(row + 8) * N_S + col) = hi;
        }
    }
}

// ---------------------------------------------------------------------------
// Kernel 2: argmax, 4x4 pixel tile per block.
// Block = 256 threads = 16 pixels x 16 vs-slices (8 vs each).
// Per-block T footprint: 6x6 ref rows read once each -> 4x less L2 traffic.
// Lockstep us loop keeps the per-step working set (~18KB) L1-resident.
// ---------------------------------------------------------------------------
__device__ __forceinline__ float bf_lo(uint32_t u) { return __uint_as_float(u << 16); }
__device__ __forceinline__ float bf_hi(uint32_t u) { return __uint_as_float(u & 0xffff0000u); }

__global__ __launch_bounds__(256) void argmax_kernel() {
    const int n   = blockIdx.z;
    const int tid = threadIdx.x;
    const int px  = tid >> 4;        // 0..15
    const int sub = tid & 15;        // 0..15
    const int di  = px >> 2;
    const int dj  = px & 3;
    const int i   = blockIdx.y * 4 + di;
    const int j   = blockIdx.x * 4 + dj;
    const int vs0 = sub << 3;        // 0..120

    float best = -FLT_MAX;
    int   bidx = 0;
    const bool valid = (i < HP) && (j < HP);

    if (valid) {
        const __nv_bfloat16* Tn = g_Tb + (size_t)n * M_R * N_S;
        const __nv_bfloat16* rp[3][3];
#pragma unroll
        for (int a = 0; a < 3; a++)
#pragma unroll
            for (int b = 0; b < 3; b++)
                rp[a][b] = Tn + (size_t)((i + a) * WW + (j + b)) * N_S + vs0;

        const bool tail = (sub == 15);       // vs0 == 120: only d<6 valid, no +8 load

        for (int us = 0; us < USZ; us++) {
            float s[8];
#pragma unroll
            for (int d = 0; d < 8; d++) s[d] = 0.0f;

#pragma unroll
            for (int a = 0; a < 3; a++) {
                const int off = (us + a) * WS;
#pragma unroll
                for (int b = 0; b < 3; b++) {
                    const __nv_bfloat16* p = rp[a][b] + off;
                    uint4 v = *(const uint4*)p;
                    float f[10];
                    f[0] = bf_lo(v.x); f[1] = bf_hi(v.x);
                    f[2] = bf_lo(v.y); f[3] = bf_hi(v.y);
                    f[4] = bf_lo(v.z); f[5] = bf_hi(v.z);
                    f[6] = bf_lo(v.w); f[7] = bf_hi(v.w);
                    if (!tail) {
                        uint32_t t = *(const uint32_t*)(p + 8);
                        f[8] = bf_lo(t); f[9] = bf_hi(t);
                    } else {
                        f[8] = 0.0f; f[9] = 0.0f;
                    }
#pragma unroll
                    for (int d = 0; d < 8; d++) s[d] += f[b + d];
                }
            }

            const int ubase = us * USZ + vs0;
            const int dmax  = tail ? 6 : 8;
#pragma unroll
            for (int d = 0; d < 8; d++) {
                if (d < dmax && s[d] > best) { best = s[d]; bidx = ubase + d; }
            }
        }
    }

    // Per-pixel reduction: 16 consecutive lanes -> xor-shuffle within half warp.
#pragma unroll
    for (int off = 8; off > 0; off >>= 1) {
        float ov = __shfl_xor_sync(0xffffffffu, best, off);
        int   oi = __shfl_xor_sync(0xffffffffu, bidx, off);
        if (ov > best || (ov == best && oi < bidx)) { best = ov; bidx = oi; }
    }
    if (valid && sub == 0)
        g_idx[(n * HP + i) * HP + j] = bidx;
}

// ---------------------------------------------------------------------------
// Kernel 3: gather matched color patch, L1 vs output patch, clip, global sum.
// ---------------------------------------------------------------------------
__global__ __launch_bounds__(256) void l1_kernel(const float* __restrict__ outf,
                                                 const float* __restrict__ colf,
                                                 float* __restrict__ dout) {
    const int i = blockIdx.x;
    const int n = blockIdx.y;

    __shared__ float l1s[HP];
    __shared__ int   uu[HP];
    if (threadIdx.x < HP) {
        l1s[threadIdx.x] = 0.0f;
        uu[threadIdx.x]  = g_idx[(n * HP + i) * HP + threadIdx.x];
    }
    __syncthreads();

    for (int t = threadIdx.x; t < CC * HP; t += 256) {
        int c = t / HP;
        int j = t - c * HP;
        int u  = uu[j];
        int us = u / USZ;
        int vs = u - us * USZ;

        const float* op = outf + ((size_t)(n * CC + c) * HH + i)  * WW + j;
        const float* cp = colf + ((size_t)(n * CC + c) * HS + us) * WS + vs;

        float s = 0.0f;
#pragma unroll
        for (int a = 0; a < 3; a++)
#pragma unroll
            for (int b = 0; b < 3; b++)
                s += fabsf(op[a * WW + b] - cp[a * WS + b]);
        atomicAdd(&l1s[j], s);
    }
    __syncthreads();

    if (threadIdx.x < HP) {
        float v = fminf(fmaxf(l1s[threadIdx.x], 0.0f), 1000.0f);
        atomicAdd(dout, v);
    }
}

// ---------------------------------------------------------------------------
// Launch
// Inputs (metadata order): 0 output_feat, 1 ref_feat, 2 shape_feat, 3 color_feat
// ---------------------------------------------------------------------------
extern "C" void kernel_launch(void* const* d_in, const int* in_sizes, int n_in,
                              void* d_out, int out_size) {
    const float* output_feat = (const float*)d_in[0];
    const float* ref_feat    = (const float*)d_in[1];
    const float* shape_feat  = (const float*)d_in[2];
    const float* color_feat  = (const float*)d_in[3];
    float* out = (float*)d_out;

    zero_kernel<<<1, 32>>>(out, out_size);

    pack_kernel<<<256, 256>>>(ref_feat,   g_Apk, M_R, NB * (CC / 2) * M_R);
    pack_kernel<<<512, 256>>>(shape_feat, g_Bpk, N_S, NB * (CC / 2) * N_S);

    dim3 g1(N_S / BN, M_R / BM, NB);            // 128 x 32 x 2
    gemm_kernel<<<g1, 256>>>();

    dim3 g2((HP + 3) / 4, (HP + 3) / 4, NB);    // 16 x 16 x 2
    argmax_kernel<<<g2, 256>>>();

    dim3 g3(HP, NB);                            // 62 x 2
    l1_kernel<<<g3, 256>>>(output_feat, color_feat, out);
}